// round 9
// baseline (speedup 1.0000x reference)
#include <cuda_runtime.h>
#include <cuda_fp16.h>

// Problem constants
#define NN     512
#define NE     5
#define NL     12
#define MB     8192                 // 16 channels * 512 rows
#define SCALE  1.953125e-5f         // SAMPLE_SIZE_CM / N = 0.01/512
#define KFAC   170.0f               // PROBE_CTS * FL_RATIO * SA_ADJ * SA_THETA

// Pass-A tiling: 64x32 output tile (proven shape)
#define NCHUNK 8                    // 512 / 64 chunks per row
#define CHG    74                   // bbox rows capacity incl. guard: 72.2+1
#define CWQ    81                   // uint4 row stride (odd: diagonal bank skew); cap 76+4 guard

#define SMEM_BYTES (CHG * CWQ * 16)   // 95904

// scratch: per (row b, chunk): [T, S0..S4]
__device__ float g_scratch[MB * NCHUNK * 6];

// ───────────────────────────── Pass A: rotate + sample + chunk partials ─────
__global__ __launch_bounds__(512, 2) void ppm_passA(
    const float* __restrict__ xp,        // (5, 16, 512, 512)
    const float* __restrict__ attCS,     // (5,)
    const float* __restrict__ theta_p)   // (1,)
{
    extern __shared__ uint4 smQ[];       // [CHG][CWQ]: 8 halves = e0,e1,e2,e3,e4,lac,pad,pad

    const int tid  = threadIdx.x;
    const int lane = tid & 31;
    const int warp = tid >> 5;          // 0..15

    const int bid = blockIdx.x;         // 16c * 8tx * 16ty = 2048
    const int c   = bid >> 7;
    const int tx  = (bid >> 4) & 7;
    const int ty  = bid & 15;
    const int w0  = tx << 6;            // tile origin
    const int h0  = ty << 5;

    float sn, cs;
    sincosf(theta_p[0], &sn, &cs);
    const float inv = 1.0f / (float)NN;

    // ---- source bbox from the 4 tile corners (affine => corners suffice) ----
    float mnx = 1e30f, mxx = -1e30f, mny = 1e30f, mxy = -1e30f;
#pragma unroll
    for (int k = 0; k < 4; k++) {
        const int wv = w0 + ((k & 1) ? 63 : 0);
        const int hv = h0 + ((k & 2) ? 31 : 0);
        const float gx = (2.0f * (float)wv + 1.0f) * inv - 1.0f;
        const float gy = (2.0f * (float)hv + 1.0f) * inv - 1.0f;
        float ix = ((cs * gx - sn * gy + 1.0f) * (float)NN - 1.0f) * 0.5f;
        float iy = ((sn * gx + cs * gy + 1.0f) * (float)NN - 1.0f) * 0.5f;
        ix = fminf(fmaxf(ix, 0.0f), (float)(NN - 1));
        iy = fminf(fmaxf(iy, 0.0f), (float)(NN - 1));
        mnx = fminf(mnx, ix); mxx = fmaxf(mxx, ix);
        mny = fminf(mny, iy); mxy = fmaxf(mxy, iy);
    }
    const int xs0 = (int)floorf(mnx);
    const int ys0 = (int)floorf(mny);
    const int xq0 = xs0 & ~3;                    // 16B-aligned staging origin
    const int bw  = min(min((int)floorf(mxx) + 1, NN - 1) - xq0 + 1, CWQ - 5);
    const int bh  = min(min((int)floorf(mxy) + 1, NN - 1) - ys0 + 1, CHG - 1);

    const float a0 = __ldg(attCS + 0), a1 = __ldg(attCS + 1), a2 = __ldg(attCS + 2),
                a3 = __ldg(attCS + 3), a4 = __ldg(attCS + 4);

    // ---- stage bbox (+1 guard row, +1 guard quad): LDG.128 -> half pack + lac ----
    const float* __restrict__ pc = xp + ((size_t)c << 18);
    {
        const int nq  = ((bw + 3) >> 2) + 1;    // column quads incl. guard
        const int tot = (bh + 1) * nq;          // rows incl. guard
        for (int i = tid; i < tot; i += 512) {
            const int y = i / nq;
            const int q = i - y * nq;
            const int gy = min(ys0 + y, NN - 1);          // guard row: clamped dup
            const int sx = min(xq0 + (q << 2), NN - 4);   // guard quad: clamped dup (aligned)
            const float* p = pc + ((size_t)gy << 9) + sx;
            float4 v0 = *(const float4*)(p);
            float4 v1 = *(const float4*)(p + (1u << 22));
            float4 v2 = *(const float4*)(p + (2u << 22));
            float4 v3 = *(const float4*)(p + (3u << 22));
            float4 v4 = *(const float4*)(p + ((size_t)4 << 22));
            const float* f0 = (const float*)&v0;
            const float* f1 = (const float*)&v1;
            const float* f2 = (const float*)&v2;
            const float* f3 = (const float*)&v3;
            const float* f4 = (const float*)&v4;
            const int xb = y * CWQ + (q << 2);
#pragma unroll
            for (int k = 0; k < 4; k++) {
                const float lac = a0 * f0[k] + a1 * f1[k] + a2 * f2[k]
                                + a3 * f3[k] + a4 * f4[k];
                __half2 p01 = __floats2half2_rn(f0[k], f1[k]);
                __half2 p23 = __floats2half2_rn(f2[k], f3[k]);
                __half2 p45 = __floats2half2_rn(f4[k], lac);
                uint4 pk;
                pk.x = *(unsigned int*)&p01;
                pk.y = *(unsigned int*)&p23;
                pk.z = *(unsigned int*)&p45;
                pk.w = 0u;
                smQ[xb + k] = pk;
            }
        }
    }
    __syncthreads();

    // ---- 2 sweeps: warp handles tile rows (warp) and (warp+16); lane = 2 adjacent w ----
#pragma unroll
    for (int sweep = 0; sweep < 2; sweep++) {
        const int r = warp + (sweep << 4);        // 0..31
        const int h = h0 + r;
        const int b = (c << 9) + h;
        const float gy = (2.0f * (float)h + 1.0f) * inv - 1.0f;
        const float sgy = sn * gy, cgy = cs * gy;

        float conc[2][5];
        float lacv[2];
#pragma unroll
        for (int j = 0; j < 2; j++) {
            const int w = w0 + (lane << 1) + j;
            const float gx = (2.0f * (float)w + 1.0f) * inv - 1.0f;
            float ix = ((cs * gx - sgy + 1.0f) * (float)NN - 1.0f) * 0.5f;
            float iy = ((sn * gx + cgy + 1.0f) * (float)NN - 1.0f) * 0.5f;
            ix = fminf(fmaxf(ix, 0.0f), (float)(NN - 1));
            iy = fminf(fmaxf(iy, 0.0f), (float)(NN - 1));
            const float x0f = floorf(ix);
            const float y0f = floorf(iy);
            const float wx = ix - x0f;
            const float wy = iy - y0f;
            const float w00 = (1.0f - wx) * (1.0f - wy);
            const float w01 = wx * (1.0f - wy);
            const float w10 = (1.0f - wx) * wy;
            const float w11 = wx * wy;

            // guard row/col make +1 offsets always valid (zero-weight when clamped)
            const int A = ((int)y0f - ys0) * CWQ + ((int)x0f - xq0);
            const uint4 t00 = smQ[A];
            const uint4 t01 = smQ[A + 1];
            const uint4 t10 = smQ[A + CWQ];
            const uint4 t11 = smQ[A + CWQ + 1];

            const float2 a00 = __half22float2(*(const __half2*)&t00.x);
            const float2 b00 = __half22float2(*(const __half2*)&t00.y);
            const float2 c00 = __half22float2(*(const __half2*)&t00.z);
            const float2 a01 = __half22float2(*(const __half2*)&t01.x);
            const float2 b01 = __half22float2(*(const __half2*)&t01.y);
            const float2 c01 = __half22float2(*(const __half2*)&t01.z);
            const float2 a10 = __half22float2(*(const __half2*)&t10.x);
            const float2 b10 = __half22float2(*(const __half2*)&t10.y);
            const float2 c10 = __half22float2(*(const __half2*)&t10.z);
            const float2 a11 = __half22float2(*(const __half2*)&t11.x);
            const float2 b11 = __half22float2(*(const __half2*)&t11.y);
            const float2 c11 = __half22float2(*(const __half2*)&t11.z);

            conc[j][0] = w00 * a00.x + w01 * a01.x + w10 * a10.x + w11 * a11.x;
            conc[j][1] = w00 * a00.y + w01 * a01.y + w10 * a10.y + w11 * a11.y;
            conc[j][2] = w00 * b00.x + w01 * b01.x + w10 * b10.x + w11 * b11.x;
            conc[j][3] = w00 * b00.y + w01 * b01.y + w10 * b10.y + w11 * b11.y;
            conc[j][4] = w00 * c00.x + w01 * c01.x + w10 * c10.x + w11 * c11.x;
            lacv[j]    = w00 * c00.y + w01 * c01.y + w10 * c10.y + w11 * c11.y;
        }

        // warp inclusive scan of lane pair-sums -> local exclusive prefix within chunk
        const float pairsum = lacv[0] + lacv[1];
        float psc = pairsum;
#pragma unroll
        for (int o = 1; o < 32; o <<= 1) {
            const float n = __shfl_up_sync(0xffffffffu, psc, o);
            if (lane >= o) psc += n;
        }
        const float excl0 = psc - pairsum;
        const float at0 = __expf(-excl0 * SCALE);
        const float at1 = __expf(-(excl0 + lacv[0]) * SCALE);

        // locally attenuated per-element sums over the 64-wide chunk
        float S[NE];
#pragma unroll
        for (int e = 0; e < NE; e++) {
            float s = at0 * conc[0][e] + at1 * conc[1][e];
#pragma unroll
            for (int o = 16; o > 0; o >>= 1)
                s += __shfl_xor_sync(0xffffffffu, s, o);
            S[e] = s;
        }
        const float T = __shfl_sync(0xffffffffu, psc, 31);  // chunk lac total

        if (lane < 6) {
            float v = T;
            if (lane == 1) v = S[0];
            else if (lane == 2) v = S[1];
            else if (lane == 3) v = S[2];
            else if (lane == 4) v = S[3];
            else if (lane == 5) v = S[4];
            g_scratch[((size_t)(b << 3) + tx) * 6 + lane] = v;
        }
    }
}

// ───────────────────────────── Pass B: cross-chunk combine + outputs ────────
__global__ __launch_bounds__(256) void ppm_passB(
    const float* __restrict__ dfu,       // (12,)
    const int*   __restrict__ lidx,      // (12,)
    float* __restrict__ out)
{
    const int tid  = threadIdx.x;
    const int lane = tid & 31;
    const int warp = tid >> 5;
    const int b    = (blockIdx.x << 3) + warp;     // one row per warp

    float T = 0.0f, S0 = 0.0f, S1 = 0.0f, S2 = 0.0f, S3 = 0.0f, S4 = 0.0f;
    if (lane < NCHUNK) {
        const float* p = g_scratch + ((size_t)(b << 3) + lane) * 6;
        T  = p[0]; S0 = p[1]; S1 = p[2]; S2 = p[3]; S3 = p[4]; S4 = p[5];
    }
    float incl = T;
#pragma unroll
    for (int o = 1; o < 8; o <<= 1) {
        const float n = __shfl_up_sync(0xffffffffu, incl, o, 8);
        if ((lane & 7) >= o) incl += n;
    }
    const float wfac = __expf(-(incl - T) * SCALE);   // exp(-chunk prefix)
    float t0 = wfac * S0, t1 = wfac * S1, t2 = wfac * S2, t3 = wfac * S3, t4 = wfac * S4;
#pragma unroll
    for (int o = 4; o > 0; o >>= 1) {
        t0 += __shfl_xor_sync(0xffffffffu, t0, o, 8);
        t1 += __shfl_xor_sync(0xffffffffu, t1, o, 8);
        t2 += __shfl_xor_sync(0xffffffffu, t2, o, 8);
        t3 += __shfl_xor_sync(0xffffffffu, t3, o, 8);
        t4 += __shfl_xor_sync(0xffffffffu, t4, o, 8);
    }
    const float Ttot = __shfl_sync(0xffffffffu, incl, 7, 8);

    if (lane < 8) {
#pragma unroll
        for (int rep = 0; rep < 2; rep++) {
            const int idx = lane + (rep << 3);
            if (idx < NL) {
                const int e = __ldg(lidx + idx);
                float se = t0;
                if (e == 1) se = t1; else if (e == 2) se = t2;
                else if (e == 3) se = t3; else if (e == 4) se = t4;
                out[idx * MB + b] = KFAC * __ldg(dfu + idx) * se;
            } else if (idx == NL) {
                out[NL * MB + b] = Ttot * SCALE;   // transmission
            }
        }
    }
}

extern "C" void kernel_launch(void* const* d_in, const int* in_sizes, int n_in,
                              void* d_out, int out_size)
{
    const float* xp      = (const float*)d_in[0];
    const float* attCS   = (const float*)d_in[1];
    const float* dfu     = (const float*)d_in[2];
    const float* theta_p = (const float*)d_in[3];
    const int*   lidx    = (const int*)d_in[4];
    float* out = (float*)d_out;

    static bool attr_set = false;
    if (!attr_set) {
        cudaFuncSetAttribute(ppm_passA, cudaFuncAttributeMaxDynamicSharedMemorySize,
                             SMEM_BYTES);
        attr_set = true;
    }
    ppm_passA<<<2048, 512, SMEM_BYTES>>>(xp, attCS, theta_p);
    ppm_passB<<<MB / 8, 256>>>(dfu, lidx, out);
}

// round 10
// speedup vs baseline: 1.3720x; 1.3720x over previous
#include <cuda_runtime.h>
#include <cuda_fp16.h>

// Problem constants
#define NN     512
#define NE     5
#define NL     12
#define MB     8192                 // 16 channels * 512 rows
#define SCALE  1.953125e-5f         // SAMPLE_SIZE_CM / N = 0.01/512
#define KFAC   170.0f               // PROBE_CTS * FL_RATIO * SA_ADJ * SA_THETA

// Pass-A tiling: 64x64 output tile (fp16 split layout, 512 threads, 2 blocks/SM)
#define NCHUNK 8                    // 512 / 64 chunks per row
#define CH     95                   // bbox rows: worst-case 64*sqrt(2)+2 = 92.5 (+margin)
#define CWS    97                   // half4 (uint2) row stride, odd for bank skew; cap 93+3 align
#define CWE    100                  // e4 half row stride (mult of 4 halves = 8B)

#define SMK_BYTES (CH * CWS * 8)    // 73720
#define SMEM_BYTES (SMK_BYTES + CH * CWE * 2)   // + 19000 = 92720

// scratch: per (row b, chunk): [T, S0..S4]
__device__ float g_scratch[MB * NCHUNK * 6];

// ───────────────────────────── Pass A: rotate + sample + chunk partials ─────
__global__ __launch_bounds__(512, 2) void ppm_passA(
    const float* __restrict__ xp,        // (5, 16, 512, 512)
    const float* __restrict__ attCS,     // (5,)
    const float* __restrict__ theta_p)   // (1,)
{
    extern __shared__ char dyn[];
    uint2*  smK = (uint2*)dyn;                    // [CH][CWS] half4 of e0..e3
    __half* smE = (__half*)(dyn + SMK_BYTES);     // [CH][CWE] e4

    const int tid  = threadIdx.x;
    const int lane = tid & 31;
    const int warp = tid >> 5;                  // 0..15

    const int bid = blockIdx.x;                 // 16c * 8tx * 8ty = 1024
    const int c   = bid >> 6;
    const int tx  = (bid >> 3) & 7;
    const int ty  = bid & 7;
    const int w0  = tx << 6;                    // tile origin
    const int h0  = ty << 6;

    float sn, cs;
    sincosf(theta_p[0], &sn, &cs);
    const float inv = 1.0f / (float)NN;

    // ---- source bbox from the 4 tile corners (affine => corners suffice) ----
    float mnx = 1e30f, mxx = -1e30f, mny = 1e30f, mxy = -1e30f;
#pragma unroll
    for (int k = 0; k < 4; k++) {
        const int wv = w0 + ((k & 1) ? 63 : 0);
        const int hv = h0 + ((k & 2) ? 63 : 0);
        const float gx = (2.0f * (float)wv + 1.0f) * inv - 1.0f;
        const float gy = (2.0f * (float)hv + 1.0f) * inv - 1.0f;
        float ix = ((cs * gx - sn * gy + 1.0f) * (float)NN - 1.0f) * 0.5f;
        float iy = ((sn * gx + cs * gy + 1.0f) * (float)NN - 1.0f) * 0.5f;
        ix = fminf(fmaxf(ix, 0.0f), (float)(NN - 1));
        iy = fminf(fmaxf(iy, 0.0f), (float)(NN - 1));
        mnx = fminf(mnx, ix); mxx = fmaxf(mxx, ix);
        mny = fminf(mny, iy); mxy = fmaxf(mxy, iy);
    }
    const int xs0 = (int)floorf(mnx);
    const int ys0 = (int)floorf(mny);
    const int xq0 = xs0 & ~3;                    // 16B-aligned staging origin
    const int bw  = min(min((int)floorf(mxx) + 1, NN - 1) - xq0 + 1, CWS - 1);
    const int bh  = min(min((int)floorf(mxy) + 1, NN - 1) - ys0 + 1, CH);

    // ---- stage bbox, 5 elements, aligned LDG.128 -> half pack -> STS.64 ----
    const float* __restrict__ pc = xp + ((size_t)c << 18);
    {
        const int nq  = (bw + 3) >> 2;          // column quads; aligned, never OOB (NN%4==0)
        const int tot = bh * nq;
        for (int i = tid; i < tot; i += 512) {
            const int y = i / nq;
            const int q = i - y * nq;
            const int gy = ys0 + y;             // <= NN-1 for y < bh
            const int sx = xq0 + (q << 2);
            const float* p = pc + ((size_t)gy << 9) + sx;
            float4 v0 = *(const float4*)(p);
            float4 v1 = *(const float4*)(p + (1u << 22));
            float4 v2 = *(const float4*)(p + (2u << 22));
            float4 v3 = *(const float4*)(p + (3u << 22));
            float4 v4 = *(const float4*)(p + ((size_t)4 << 22));
            const float* f0 = (const float*)&v0;
            const float* f1 = (const float*)&v1;
            const float* f2 = (const float*)&v2;
            const float* f3 = (const float*)&v3;
            const int xb = q << 2;
#pragma unroll
            for (int k = 0; k < 4; k++) {
                __half2 p01 = __floats2half2_rn(f0[k], f1[k]);
                __half2 p23 = __floats2half2_rn(f2[k], f3[k]);
                uint2 pk;
                pk.x = *(unsigned int*)&p01;
                pk.y = *(unsigned int*)&p23;
                smK[y * CWS + xb + k] = pk;
            }
            __half2 e01 = __floats2half2_rn(v4.x, v4.y);
            __half2 e23 = __floats2half2_rn(v4.z, v4.w);
            uint2 ek;
            ek.x = *(unsigned int*)&e01;
            ek.y = *(unsigned int*)&e23;
            *(uint2*)(smE + y * CWE + xb) = ek;   // 8B-aligned: CWE%4==0, xb%4==0
        }
    }

    const float a0 = __ldg(attCS + 0), a1 = __ldg(attCS + 1), a2 = __ldg(attCS + 2),
                a3 = __ldg(attCS + 3), a4 = __ldg(attCS + 4);
    __syncthreads();

    // ---- 4 sweeps: warp handles tile rows warp+16k; lane = 2 adjacent w ----
#pragma unroll
    for (int sweep = 0; sweep < 4; sweep++) {
        const int r = warp + (sweep << 4);        // 0..63
        const int h = h0 + r;
        const int b = (c << 9) + h;
        const float gy = (2.0f * (float)h + 1.0f) * inv - 1.0f;
        const float sgy = sn * gy, cgy = cs * gy;

        float conc[2][5];
        float lacv[2];
#pragma unroll
        for (int j = 0; j < 2; j++) {
            const int w = w0 + (lane << 1) + j;
            const float gx = (2.0f * (float)w + 1.0f) * inv - 1.0f;
            float ix = ((cs * gx - sgy + 1.0f) * (float)NN - 1.0f) * 0.5f;
            float iy = ((sn * gx + cgy + 1.0f) * (float)NN - 1.0f) * 0.5f;
            ix = fminf(fmaxf(ix, 0.0f), (float)(NN - 1));
            iy = fminf(fmaxf(iy, 0.0f), (float)(NN - 1));
            const float x0f = floorf(ix);
            const float y0f = floorf(iy);
            const float wx = ix - x0f;
            const float wy = iy - y0f;
            const int lx0 = (int)x0f - xq0;
            const int ly0 = (int)y0f - ys0;
            const int lx1 = min((int)x0f + 1, NN - 1) - xq0;
            const int ly1 = min((int)y0f + 1, NN - 1) - ys0;
            const float w00 = (1.0f - wx) * (1.0f - wy);
            const float w01 = wx * (1.0f - wy);
            const float w10 = (1.0f - wx) * wy;
            const float w11 = wx * wy;

            const uint2 u00 = smK[ly0 * CWS + lx0];
            const uint2 u01 = smK[ly0 * CWS + lx1];
            const uint2 u10 = smK[ly1 * CWS + lx0];
            const uint2 u11 = smK[ly1 * CWS + lx1];
            const float e00 = __half2float(smE[ly0 * CWE + lx0]);
            const float e01 = __half2float(smE[ly0 * CWE + lx1]);
            const float e10 = __half2float(smE[ly1 * CWE + lx0]);
            const float e11 = __half2float(smE[ly1 * CWE + lx1]);

            const float2 a00 = __half22float2(*(const __half2*)&u00.x);
            const float2 b00 = __half22float2(*(const __half2*)&u00.y);
            const float2 a01 = __half22float2(*(const __half2*)&u01.x);
            const float2 b01 = __half22float2(*(const __half2*)&u01.y);
            const float2 a10 = __half22float2(*(const __half2*)&u10.x);
            const float2 b10 = __half22float2(*(const __half2*)&u10.y);
            const float2 a11 = __half22float2(*(const __half2*)&u11.x);
            const float2 b11 = __half22float2(*(const __half2*)&u11.y);

            conc[j][0] = w00 * a00.x + w01 * a01.x + w10 * a10.x + w11 * a11.x;
            conc[j][1] = w00 * a00.y + w01 * a01.y + w10 * a10.y + w11 * a11.y;
            conc[j][2] = w00 * b00.x + w01 * b01.x + w10 * b10.x + w11 * b11.x;
            conc[j][3] = w00 * b00.y + w01 * b01.y + w10 * b10.y + w11 * b11.y;
            conc[j][4] = w00 * e00   + w01 * e01   + w10 * e10   + w11 * e11;
            lacv[j] = a0 * conc[j][0] + a1 * conc[j][1] + a2 * conc[j][2]
                    + a3 * conc[j][3] + a4 * conc[j][4];
        }

        // warp inclusive scan of lane pair-sums -> local exclusive prefix within chunk
        const float pairsum = lacv[0] + lacv[1];
        float psc = pairsum;
#pragma unroll
        for (int o = 1; o < 32; o <<= 1) {
            const float n = __shfl_up_sync(0xffffffffu, psc, o);
            if (lane >= o) psc += n;
        }
        const float excl0 = psc - pairsum;
        const float at0 = __expf(-excl0 * SCALE);
        const float at1 = __expf(-(excl0 + lacv[0]) * SCALE);

        // locally attenuated per-element sums over the 64-wide chunk
        float S[NE];
#pragma unroll
        for (int e = 0; e < NE; e++) {
            float s = at0 * conc[0][e] + at1 * conc[1][e];
#pragma unroll
            for (int o = 16; o > 0; o >>= 1)
                s += __shfl_xor_sync(0xffffffffu, s, o);
            S[e] = s;
        }
        const float T = __shfl_sync(0xffffffffu, psc, 31);  // chunk lac total

        if (lane < 6) {
            float v = T;
            if (lane == 1) v = S[0];
            else if (lane == 2) v = S[1];
            else if (lane == 3) v = S[2];
            else if (lane == 4) v = S[3];
            else if (lane == 5) v = S[4];
            g_scratch[((size_t)(b << 3) + tx) * 6 + lane] = v;
        }
    }
}

// ───────────────────────────── Pass B: cross-chunk combine + outputs ────────
__global__ __launch_bounds__(256) void ppm_passB(
    const float* __restrict__ dfu,       // (12,)
    const int*   __restrict__ lidx,      // (12,)
    float* __restrict__ out)
{
    const int tid  = threadIdx.x;
    const int lane = tid & 31;
    const int warp = tid >> 5;
    const int b    = (blockIdx.x << 3) + warp;     // one row per warp

    float T = 0.0f, S0 = 0.0f, S1 = 0.0f, S2 = 0.0f, S3 = 0.0f, S4 = 0.0f;
    if (lane < NCHUNK) {
        const float* p = g_scratch + ((size_t)(b << 3) + lane) * 6;
        T  = p[0]; S0 = p[1]; S1 = p[2]; S2 = p[3]; S3 = p[4]; S4 = p[5];
    }
    float incl = T;
#pragma unroll
    for (int o = 1; o < 8; o <<= 1) {
        const float n = __shfl_up_sync(0xffffffffu, incl, o, 8);
        if ((lane & 7) >= o) incl += n;
    }
    const float wfac = __expf(-(incl - T) * SCALE);   // exp(-chunk prefix)
    float t0 = wfac * S0, t1 = wfac * S1, t2 = wfac * S2, t3 = wfac * S3, t4 = wfac * S4;
#pragma unroll
    for (int o = 4; o > 0; o >>= 1) {
        t0 += __shfl_xor_sync(0xffffffffu, t0, o, 8);
        t1 += __shfl_xor_sync(0xffffffffu, t1, o, 8);
        t2 += __shfl_xor_sync(0xffffffffu, t2, o, 8);
        t3 += __shfl_xor_sync(0xffffffffu, t3, o, 8);
        t4 += __shfl_xor_sync(0xffffffffu, t4, o, 8);
    }
    const float Ttot = __shfl_sync(0xffffffffu, incl, 7, 8);

    if (lane < 8) {
#pragma unroll
        for (int rep = 0; rep < 2; rep++) {
            const int idx = lane + (rep << 3);
            if (idx < NL) {
                const int e = __ldg(lidx + idx);
                float se = t0;
                if (e == 1) se = t1; else if (e == 2) se = t2;
                else if (e == 3) se = t3; else if (e == 4) se = t4;
                out[idx * MB + b] = KFAC * __ldg(dfu + idx) * se;
            } else if (idx == NL) {
                out[NL * MB + b] = Ttot * SCALE;   // transmission
            }
        }
    }
}

extern "C" void kernel_launch(void* const* d_in, const int* in_sizes, int n_in,
                              void* d_out, int out_size)
{
    const float* xp      = (const float*)d_in[0];
    const float* attCS   = (const float*)d_in[1];
    const float* dfu     = (const float*)d_in[2];
    const float* theta_p = (const float*)d_in[3];
    const int*   lidx    = (const int*)d_in[4];
    float* out = (float*)d_out;

    static bool attr_set = false;
    if (!attr_set) {
        cudaFuncSetAttribute(ppm_passA, cudaFuncAttributeMaxDynamicSharedMemorySize,
                             SMEM_BYTES);
        attr_set = true;
    }
    ppm_passA<<<1024, 512, SMEM_BYTES>>>(xp, attCS, theta_p);
    ppm_passB<<<MB / 8, 256>>>(dfu, lidx, out);
}